// round 7
// baseline (speedup 1.0000x reference)
#include <cuda_runtime.h>
#include <cuda_bf16.h>

// Problem constants: nw_out is [N=4, C=19, H=512, W=1024] float32.
#define NCH    19
#define NBAT   4
#define HH     512
#define WW     1024
#define HWP    (HH * WW)            // 524288 pixels per image
#define HWP2   (HWP / 2)            // 262144 float2 pairs per image-channel
#define NPIX   (NBAT * HWP)         // 2097152
#define NPAIR  (NPIX / 2)           // 1048576
#define IW_F   0.2f
#define GRID_BLOCKS 740             // 5 CTAs/SM x 148 SMs = exactly one wave

// Scratch accumulators. Zeroed at module load; the fused finalize re-zeroes
// them after consuming, so every graph replay starts from zero.
__device__ float        g_sum[NCH] = {};
__device__ unsigned int g_cnt[NCH] = {};
__device__ unsigned int g_done     = 0;

__global__ __launch_bounds__(256) void msiw_kernel(const float2* __restrict__ x2,
                                                   float* __restrict__ out) {
    __shared__ float        s_sum[NCH];
    __shared__ unsigned int s_cnt[NCH];
    if (threadIdx.x < NCH) {
        s_sum[threadIdx.x] = 0.0f;
        s_cnt[threadIdx.x] = 0u;
    }
    __syncthreads();

    const int stride = GRID_BLOCKS * 256;          // in float2 pairs
    for (int q = blockIdx.x * blockDim.x + threadIdx.x; q < NPAIR; q += stride) {
        const int n   = q / HWP2;                  // batch index
        const int hw2 = q - n * HWP2;              // pair position within image
        const float2* base = x2 + (size_t)n * (NCH * HWP2) + hw2;

        // Load all 19 channels as float2, FORCED front-batched: asm volatile
        // loads cannot be reordered/sunk by nvcc or ptxas, so all 19 LDG.64
        // issue back-to-back (MLP ~19, 38 value regs live) regardless of how
        // the consumers below are scheduled. (R4/R5 lesson: liveness, not
        // source order, controls batching — so force it.)
        float vx[NCH], vy[NCH];
#pragma unroll
        for (int c = 0; c < NCH; c++) {
            const float2* p = base + (size_t)c * HWP2;
            asm volatile("ld.global.v2.f32 {%0, %1}, [%2];"
                         : "=f"(vx[c]), "=f"(vy[c]) : "l"(p));
        }

        // r = sum_c softmax^2 = s2/s1^2, WITHOUT max shift (shift-invariant;
        // inputs ~N(0,1) so e^v is safely inside fp32 range). The MUFU chain
        // is independent of the argmax select chain and overlaps it.
        float s1x = 0.f, s2x = 0.f, s1y = 0.f, s2y = 0.f;
#pragma unroll
        for (int c = 0; c < NCH; c++) {
            float ex = __expf(vx[c]);
            float ey = __expf(vy[c]);
            s1x += ex; s2x = fmaf(ex, ex, s2x);
            s1y += ey; s2y = fmaf(ey, ey, s2y);
        }

        // Per-component argmax (strict > keeps first-max semantics).
        float mx = vx[0], my = vy[0];
        int ix = 0, iy = 0;
#pragma unroll
        for (int c = 1; c < NCH; c++) {
            if (vx[c] > mx) { mx = vx[c]; ix = c; }
            if (vy[c] > my) { my = vy[c]; iy = c; }
        }

        atomicAdd(&s_sum[ix], __fdividef(s2x, s1x * s1x));
        atomicAdd(&s_sum[iy], __fdividef(s2y, s1y * s1y));
        atomicAdd(&s_cnt[ix], 1u);
        atomicAdd(&s_cnt[iy], 1u);
    }

    __syncthreads();
    if (threadIdx.x < NCH) {
        atomicAdd(&g_sum[threadIdx.x], s_sum[threadIdx.x]);
        atomicAdd(&g_cnt[threadIdx.x], s_cnt[threadIdx.x]);
    }

    // ---- fused finalize: last block to finish does the 19-term reduction ----
    __threadfence();                               // make bin atomics visible
    __shared__ unsigned int s_last;
    if (threadIdx.x == 0) {
        unsigned int ticket = atomicAdd(&g_done, 1u);
        s_last = (ticket == gridDim.x - 1) ? 1u : 0u;
    }
    __syncthreads();
    if (s_last && threadIdx.x < 32) {
        int c = threadIdx.x;
        float partial = 0.0f;
        if (c < NCH) {
            float cnt   = (float)g_cnt[c];
            float scale = powf((float)NPIX, 1.0f - IW_F);        // Np^0.8
            float den   = fmaxf(powf(cnt, IW_F) * scale, 1.0f);  // max(hist^0.2*Np^0.8, 1)
            partial = g_sum[c] / den;
            g_sum[c] = 0.0f;                                     // reset for next replay
            g_cnt[c] = 0u;
        }
#pragma unroll
        for (int o = 16; o > 0; o >>= 1)
            partial += __shfl_down_sync(0xffffffffu, partial, o);
        if (c == 0) {
            out[0] = -partial / (float)(NBAT * NCH);
            g_done = 0;                                          // reset ticket
        }
    }
}

extern "C" void kernel_launch(void* const* d_in, const int* in_sizes, int n_in,
                              void* d_out, int out_size) {
    (void)in_sizes; (void)n_in; (void)out_size;
    const float2* x2 = (const float2*)d_in[0];
    float* out = (float*)d_out;

    // Single launch, exactly one wave: 740 blocks x 256 threads; each thread
    // handles ~5.5 float2 pairs via the grid-stride loop. Finalize fused via
    // the last-block ticket.
    msiw_kernel<<<GRID_BLOCKS, 256>>>(x2, out);
}

// round 8
// speedup vs baseline: 1.2678x; 1.2678x over previous
#include <cuda_runtime.h>
#include <cuda_bf16.h>

// Problem constants: nw_out is [N=4, C=19, H=512, W=1024] float32.
#define NCH    19
#define NBAT   4
#define HH     512
#define WW     1024
#define HWP    (HH * WW)            // 524288 pixels per image
#define HWP2   (HWP / 2)            // 262144 float2 pairs per image-channel
#define NPIX   (NBAT * HWP)         // 2097152
#define NPAIR  (NPIX / 2)           // 1048576
#define IW_F   0.2f
#define GRID_BLOCKS 740             // 5 CTAs/SM x 148 SMs = exactly one wave

// Scratch accumulators. Zeroed at module load; the fused finalize re-zeroes
// them after consuming, so every graph replay starts from zero.
__device__ float        g_sum[NCH] = {};
__device__ unsigned int g_cnt[NCH] = {};
__device__ unsigned int g_done     = 0;

__global__ __launch_bounds__(256, 5) void msiw_kernel(const float2* __restrict__ x2,
                                                      float* __restrict__ out) {
    __shared__ float        s_sum[NCH];
    __shared__ unsigned int s_cnt[NCH];
    if (threadIdx.x < NCH) {
        s_sum[threadIdx.x] = 0.0f;
        s_cnt[threadIdx.x] = 0u;
    }
    __syncthreads();

    const int stride = GRID_BLOCKS * 256;          // in float2 pairs
    for (int q = blockIdx.x * blockDim.x + threadIdx.x; q < NPAIR; q += stride) {
        const int n   = q / HWP2;                  // batch index
        const int hw2 = q - n * HWP2;              // pair position within image
        const float2* base = x2 + (size_t)n * (NCH * HWP2) + hw2;

        // Load all 19 channels as float2 (256B coalesced per channel per warp).
        // R3-proven structure: the exp loop below consumes m (which depends on
        // ALL v via argmax), so every v[c] stays live through the argmax ->
        // ptxas front-batches all 19 LDG.64 (MLP ~19). The max-shift is
        // load-bearing for this; do not remove it (R5/R7 lesson).
        float2 v[NCH];
#pragma unroll
        for (int c = 0; c < NCH; c++) {
            v[c] = base[(size_t)c * HWP2];
        }

        // Per-component argmax (strict > keeps first-max semantics).
        float mx = v[0].x, my = v[0].y;
        int ix = 0, iy = 0;
#pragma unroll
        for (int c = 1; c < NCH; c++) {
            if (v[c].x > mx) { mx = v[c].x; ix = c; }
            if (v[c].y > my) { my = v[c].y; iy = c; }
        }

        // r = sum_c softmax^2 = s2 / s1^2 per component (max-shifted).
        // Packed f32x2 ops (sm_103a): shift-sub, s1-add, s2-fma each handle
        // both components in one instruction (ptxas never auto-fuses these).
        unsigned long long m2, s1p, s2p;
        asm("mov.b64 %0, {%1, %2};" : "=l"(m2) : "f"(mx), "f"(my));
        asm("mov.b64 %0, {%1, %2};" : "=l"(s1p) : "f"(0.0f), "f"(0.0f));
        asm("mov.b64 %0, {%1, %2};" : "=l"(s2p) : "f"(0.0f), "f"(0.0f));
#pragma unroll
        for (int c = 0; c < NCH; c++) {
            unsigned long long v2c, d2, e2;
            asm("mov.b64 %0, {%1, %2};" : "=l"(v2c) : "f"(v[c].x), "f"(v[c].y));
            asm("sub.rn.f32x2 %0, %1, %2;" : "=l"(d2) : "l"(v2c), "l"(m2));
            float dx, dy;
            asm("mov.b64 {%0, %1}, %2;" : "=f"(dx), "=f"(dy) : "l"(d2));
            float ex = __expf(dx);
            float ey = __expf(dy);
            asm("mov.b64 %0, {%1, %2};" : "=l"(e2) : "f"(ex), "f"(ey));
            asm("add.rn.f32x2 %0, %1, %2;" : "=l"(s1p) : "l"(s1p), "l"(e2));
            asm("fma.rn.f32x2 %0, %1, %2, %3;" : "=l"(s2p) : "l"(e2), "l"(e2), "l"(s2p));
        }
        float s1x, s1y, s2x, s2y;
        asm("mov.b64 {%0, %1}, %2;" : "=f"(s1x), "=f"(s1y) : "l"(s1p));
        asm("mov.b64 {%0, %1}, %2;" : "=f"(s2x), "=f"(s2y) : "l"(s2p));

        atomicAdd(&s_sum[ix], __fdividef(s2x, s1x * s1x));
        atomicAdd(&s_sum[iy], __fdividef(s2y, s1y * s1y));
        atomicAdd(&s_cnt[ix], 1u);
        atomicAdd(&s_cnt[iy], 1u);
    }

    __syncthreads();
    if (threadIdx.x < NCH) {
        atomicAdd(&g_sum[threadIdx.x], s_sum[threadIdx.x]);
        atomicAdd(&g_cnt[threadIdx.x], s_cnt[threadIdx.x]);
    }

    // ---- fused finalize: last block to finish does the 19-term reduction ----
    __threadfence();                               // make bin atomics visible
    __shared__ unsigned int s_last;
    if (threadIdx.x == 0) {
        unsigned int ticket = atomicAdd(&g_done, 1u);
        s_last = (ticket == gridDim.x - 1) ? 1u : 0u;
    }
    __syncthreads();
    if (s_last && threadIdx.x < 32) {
        int c = threadIdx.x;
        float partial = 0.0f;
        if (c < NCH) {
            float cnt   = (float)g_cnt[c];
            float scale = powf((float)NPIX, 1.0f - IW_F);        // Np^0.8
            float den   = fmaxf(powf(cnt, IW_F) * scale, 1.0f);  // max(hist^0.2*Np^0.8, 1)
            partial = g_sum[c] / den;
            g_sum[c] = 0.0f;                                     // reset for next replay
            g_cnt[c] = 0u;
        }
#pragma unroll
        for (int o = 16; o > 0; o >>= 1)
            partial += __shfl_down_sync(0xffffffffu, partial, o);
        if (c == 0) {
            out[0] = -partial / (float)(NBAT * NCH);
            g_done = 0;                                          // reset ticket
        }
    }
}

extern "C" void kernel_launch(void* const* d_in, const int* in_sizes, int n_in,
                              void* d_out, int out_size) {
    (void)in_sizes; (void)n_in; (void)out_size;
    const float2* x2 = (const float2*)d_in[0];
    float* out = (float*)d_out;

    // Single launch, exactly one wave: 740 blocks x 256 threads; each thread
    // handles ~5.5 float2 pairs via the grid-stride loop. Finalize fused via
    // the last-block ticket.
    msiw_kernel<<<GRID_BLOCKS, 256>>>(x2, out);
}